// round 13
// baseline (speedup 1.0000x reference)
#include <cuda_runtime.h>
#include <cuda.h>
#include <cuda_bf16.h>
#include <cstdint>

// ============================================================================
// Problem constants (fixed by setup_inputs: B=8192, D=1024, T=20, S=256)
// ============================================================================
#define D_DIM   1024
#define MAX_B   8192
#define MAX_TS  5120

#define M_TILE  64                // 2 CTAs/SM
#define N_TILE  256               // == BUFFER_SIZE -> segmented min is CTA-local
#define K_TILE  64                // int8: 64B = one SW64 atom row
#define NK      (D_DIM / K_TILE)  // 16 K-stages per tile
#define STAGES  5                 // lagged refill slack = 4 stages
#define NWC     4                 // 4 warps: 1(M) x 4(N), warp tile 64x64
#define THREADS (NWC * 32)        // 128

#define A_STAGE_BYTES (M_TILE * 64)                     // 4096
#define B_STAGE_BYTES (N_TILE * 64)                     // 16384
#define STAGE_BYTES   (A_STAGE_BYTES + B_STAGE_BYTES)   // 20480

#define SMEM_FULL   0                      // 5 x 8B mbarriers
#define SMEM_EMPTY  40                     // 5 x 8B mbarriers
#define SMEM_EPI    128                    // 2 buffers x 256 floats = 2048
#define SMEM_A      4096                   // 5 x 4096 = 20480
#define SMEM_B      (SMEM_A + STAGES * A_STAGE_BYTES)   // 24576
#define SMEM_TOTAL  (SMEM_B + STAGES * B_STAGE_BYTES)   // 106496 (x2 = 208KB/SM)

// ============================================================================
// Scratch (module-load allocation, legal under _HX_ENFORCE)
// ============================================================================
__device__ __align__(1024) int8_t g_Xq[MAX_B * D_DIM];
__device__ __align__(1024) int8_t g_Wq[MAX_TS * D_DIM];
__device__ float g_sX[MAX_B];
__device__ float g_sW[MAX_TS];

// ============================================================================
// PTX helpers (base sm_80/sm_90 ISA only — target is sm_100 base, no tcgen05)
// ============================================================================
__device__ __forceinline__ uint32_t smem_u32(const void* p) {
    uint32_t a;
    asm("{ .reg .u64 t; cvta.to.shared.u64 t, %1; cvt.u32.u64 %0, t; }"
        : "=r"(a) : "l"(p));
    return a;
}

#define MBARRIER_INIT(mbar, cnt) \
    asm volatile("mbarrier.init.shared.b64 [%0], %1;" \
                 :: "r"((uint32_t)(mbar)), "r"((uint32_t)(cnt)) : "memory")
#define MBARRIER_EXPECT_TX(mbar, bytes) \
    asm volatile("mbarrier.arrive.expect_tx.shared.b64 _, [%0], %1;" \
                 :: "r"((uint32_t)(mbar)), "r"((uint32_t)(bytes)) : "memory")
#define MBARRIER_ARRIVE(mbar) \
    asm volatile("mbarrier.arrive.shared.b64 _, [%0];" \
                 :: "r"((uint32_t)(mbar)) : "memory")

#define MBARRIER_WAIT_PARITY(mbar, parity) do {                                  \
    uint32_t _m = (uint32_t)(mbar);                                              \
    uint32_t _p = (uint32_t)(parity);                                            \
    uint32_t _done;                                                              \
    asm volatile("{\n\t.reg .pred p;\n\t"                                        \
        "mbarrier.try_wait.parity.acquire.cta.shared::cta.b64 p, [%1], %2;\n\t"  \
        "selp.b32 %0, 1, 0, p;\n\t}"                                             \
        : "=r"(_done) : "r"(_m), "r"(_p) : "memory");                            \
    if (!_done) {                                                                \
        asm volatile("{\n\t.reg .pred P1;\n\t"                                   \
            "WAIT_LOOP_%=:\n\t"                                                  \
            "mbarrier.try_wait.parity.acquire.cta.shared::cta.b64 P1, [%0], %1, 0x989680;\n\t" \
            "@P1 bra.uni WAIT_DONE_%=;\n\t"                                      \
            "bra.uni WAIT_LOOP_%=;\n\t"                                          \
            "WAIT_DONE_%=:\n\t}"                                                 \
            :: "r"(_m), "r"(_p) : "memory");                                     \
    }                                                                            \
} while (0)

#define TMA_LOAD_2D(smem_addr, tmap, cx, cy, mbar) \
    asm volatile("cp.async.bulk.tensor.2d.shared::cluster.global.tile.mbarrier::complete_tx::bytes " \
                 "[%0], [%1, {%2, %3}], [%4];" \
                 :: "r"((uint32_t)(smem_addr)), "l"(tmap), \
                    "r"((int)(cx)), "r"((int)(cy)), "r"((uint32_t)(mbar)) : "memory")

#define LDSM_X4(r0, r1, r2, r3, addr) \
    asm volatile("ldmatrix.sync.aligned.m8n8.x4.shared.b16 {%0,%1,%2,%3}, [%4];" \
                 : "=r"(r0), "=r"(r1), "=r"(r2), "=r"(r3) : "r"(addr))

// int8 IMMA: byte-identical fragment layout to HMMA m16n8k16 with f16 -> 2 x s8
#define IMMA16832(c, a, b) \
    asm volatile("mma.sync.aligned.m16n8k32.row.col.s32.s8.s8.s32 " \
                 "{%0,%1,%2,%3}, {%4,%5,%6,%7}, {%8,%9}, {%0,%1,%2,%3};" \
                 : "+r"((c)[0]), "+r"((c)[1]), "+r"((c)[2]), "+r"((c)[3]) \
                 : "r"((a)[0]), "r"((a)[1]), "r"((a)[2]), "r"((a)[3]), \
                   "r"((b)[0]), "r"((b)[1]))

// SW64 swizzle: XOR bits[5:4] with bits[8:7] (8-row x 64B atom)
#define SWZ64(x) ((x) ^ (((x) >> 3) & 0x30))

// ============================================================================
// Kernel 1: fused L2-normalize + per-row symmetric int8 quantize.
// 4 rows per 256-thread block; 64 threads/row; 4 float4 loads/thread (MLP=4).
// ============================================================================
__global__ void __launch_bounds__(256) normquant_kernel(
    const float* __restrict__ x, const float* __restrict__ w,
    int8_t* __restrict__ xq, int8_t* __restrict__ wq,
    float* __restrict__ sx, float* __restrict__ sw, int B) {
    int rid  = blockIdx.x * 4 + (threadIdx.x >> 6);
    int lane = threadIdx.x & 63;
    bool isX = rid < B;
    const float* in = isX ? x : w;
    int row = isX ? rid : rid - B;
    int8_t* outq = isX ? xq : wq;
    float* outs  = isX ? sx : sw;

    const float4* src = reinterpret_cast<const float4*>(in) + (size_t)row * 256;
    float4 v[4];
#pragma unroll
    for (int j = 0; j < 4; j++) v[j] = src[lane + j * 64];

    float ss = 0.0f, ma = 0.0f;
#pragma unroll
    for (int j = 0; j < 4; j++) {
        ss += v[j].x * v[j].x + v[j].y * v[j].y + v[j].z * v[j].z + v[j].w * v[j].w;
        ma = fmaxf(ma, fmaxf(fmaxf(fabsf(v[j].x), fabsf(v[j].y)),
                             fmaxf(fabsf(v[j].z), fabsf(v[j].w))));
    }
#pragma unroll
    for (int o = 16; o > 0; o >>= 1) {
        ss += __shfl_xor_sync(0xFFFFFFFFu, ss, o);
        ma = fmaxf(ma, __shfl_xor_sync(0xFFFFFFFFu, ma, o));
    }
    __shared__ float wss[4][2], wma[4][2];
    int rgrp = threadIdx.x >> 6;
    int wslot = (threadIdx.x >> 5) & 1;
    if ((threadIdx.x & 31) == 0) { wss[rgrp][wslot] = ss; wma[rgrp][wslot] = ma; }
    __syncthreads();
    float tot = wss[rgrp][0] + wss[rgrp][1];
    float mx  = fmaxf(wma[rgrp][0], wma[rgrp][1]);

    float rq = 127.0f / mx;
    uint32_t* dst = reinterpret_cast<uint32_t*>(outq) + (size_t)row * 256;
#pragma unroll
    for (int j = 0; j < 4; j++) {
        int q0 = __float2int_rn(v[j].x * rq), q1 = __float2int_rn(v[j].y * rq);
        int q2 = __float2int_rn(v[j].z * rq), q3 = __float2int_rn(v[j].w * rq);
        dst[lane + j * 64] = (uint32_t)(q0 & 0xFF) | ((uint32_t)(q1 & 0xFF) << 8) |
                             ((uint32_t)(q2 & 0xFF) << 16) | ((uint32_t)(q3 & 0xFF) << 24);
    }
    if (lane == 0) outs[row] = mx * rsqrtf(tot) / 127.0f;
}

// ============================================================================
// Kernel 2: PERSISTENT IMMA GEMM, 2 CTAs/SM, 128 threads (4 warps 1Mx4N,
// 64x64 warp tile). K_TILE=64 (SW64) -> 5-stage pipeline fits 2 CTAs/SM with
// lagged-refill slack of 4 stages. Co-resident CTAs decorrelate barrier and
// epilogue bubbles across SMSPs.
// ============================================================================
__global__ void __launch_bounds__(THREADS, 2) gemm_segmax_kernel(
    const __grid_constant__ CUtensorMap tma_a,
    const __grid_constant__ CUtensorMap tma_b,
    const float* __restrict__ sA, const float* __restrict__ sB,
    float* __restrict__ out, int num_tasks, int n_mtiles, int total_tiles) {
    extern __shared__ char smem[];
    uint32_t sb = smem_u32(smem);
    int tid = threadIdx.x;
    int l   = tid & 31;
    int warp_n = tid >> 5;   // 0..3 -> cols warp_n*64 (all warps share M rows)

    int ntile_cta = 0;
    for (int t = blockIdx.x; t < total_tiles; t += gridDim.x) ntile_cta++;
    if (ntile_cta == 0) return;
    int total_stg = ntile_cta * NK;

    if (tid == 0) {
#pragma unroll
        for (int s = 0; s < STAGES; s++) {
            MBARRIER_INIT(sb + SMEM_FULL  + s * 8, 1);
            MBARRIER_INIT(sb + SMEM_EMPTY + s * 8, NWC);
        }
    }
    __syncthreads();

    // ---- Prologue: fill all 5 stages (NK=16 >= 5, all within tile 0) ----
    if (tid == 0) {
        int m0p = (blockIdx.x % n_mtiles) * M_TILE;
        int n0p = (blockIdx.x / n_mtiles) * N_TILE;
#pragma unroll
        for (int gg = 0; gg < STAGES; gg++) {
            uint32_t fb = sb + SMEM_FULL + gg * 8;
            MBARRIER_EXPECT_TX(fb, STAGE_BYTES);
            TMA_LOAD_2D(sb + SMEM_A + gg * A_STAGE_BYTES, &tma_a, gg * K_TILE, m0p, fb);
            TMA_LOAD_2D(sb + SMEM_B + gg * B_STAGE_BYTES, &tma_b, gg * K_TILE, n0p, fb);
        }
    }

    // Lane-invariant byte offsets within a stage tile (row stride 64B, SW64)
    uint32_t aoff[4];
#pragma unroll
    for (int mt = 0; mt < 4; mt++)
        aoff[mt] = (uint32_t)(mt * 16 + (l & 15)) * 64 + ((l >> 4) & 1) * 16;
    uint32_t boff[4];
#pragma unroll
    for (int jp = 0; jp < 4; jp++)
        boff[jp] = (uint32_t)(warp_n * 64 + jp * 16 + ((l & 16) >> 1) + (l & 7)) * 64
                 + ((l & 8) ? 16u : 0u);

    int g = 0;                   // global stage counter
    int s = 0, ph = 0;           // consumer stage slot / parity (mod 5)
    int ps = 0, pph = 0;         // previous-iteration stage slot / parity
    int ebuf = 0;
    for (int t = blockIdx.x; t < total_tiles; t += gridDim.x) {
        int m0 = (t % n_mtiles) * M_TILE;
        int n0 = (t / n_mtiles) * N_TILE;

        int c[4][8][4];
#pragma unroll
        for (int mt = 0; mt < 4; mt++)
#pragma unroll
            for (int j = 0; j < 8; j++)
#pragma unroll
                for (int i = 0; i < 4; i++) c[mt][j][i] = 0;

#pragma unroll 1
        for (int kt = 0; kt < NK; kt++, g++) {
            uint32_t fb = sb + SMEM_FULL  + s * 8;
            uint32_t eb = sb + SMEM_EMPTY + s * 8;

            // ---- lagged refill: reload slot of stage g-1 with stage g+4 ----
            if (tid == 0 && g > 0) {
                int gr = g + STAGES - 1;           // == (g-1) + STAGES
                if (gr < total_stg) {
                    uint32_t ebp = sb + SMEM_EMPTY + ps * 8;
                    uint32_t fbp = sb + SMEM_FULL  + ps * 8;
                    MBARRIER_WAIT_PARITY(ebp, pph);
                    int tt = gr >> 4, ktt = gr & 15;   // NK = 16
                    int tgl = blockIdx.x + tt * gridDim.x;
                    MBARRIER_EXPECT_TX(fbp, STAGE_BYTES);
                    TMA_LOAD_2D(sb + SMEM_A + ps * A_STAGE_BYTES, &tma_a,
                                ktt * K_TILE, (tgl % n_mtiles) * M_TILE, fbp);
                    TMA_LOAD_2D(sb + SMEM_B + ps * B_STAGE_BYTES, &tma_b,
                                ktt * K_TILE, (tgl / n_mtiles) * N_TILE, fbp);
                }
            }

            MBARRIER_WAIT_PARITY(fb, ph);

            uint32_t a_sb = sb + SMEM_A + s * A_STAGE_BYTES;
            uint32_t b_sb = sb + SMEM_B + s * B_STAGE_BYTES;

#pragma unroll
            for (int ks = 0; ks < 2; ks++) {          // 2 x k32 per 64B stage
                uint32_t a[4][4];
#pragma unroll
                for (int mt = 0; mt < 4; mt++) {
                    uint32_t off = aoff[mt] + ks * 32;
                    LDSM_X4(a[mt][0], a[mt][1], a[mt][2], a[mt][3], a_sb + SWZ64(off));
                }
                uint32_t b[8][2];
#pragma unroll
                for (int jp = 0; jp < 4; jp++) {
                    uint32_t off = boff[jp] + ks * 32;
                    LDSM_X4(b[2 * jp][0], b[2 * jp][1], b[2 * jp + 1][0], b[2 * jp + 1][1],
                            b_sb + SWZ64(off));
                }
#pragma unroll
                for (int mt = 0; mt < 4; mt++)
#pragma unroll
                    for (int j = 0; j < 8; j++)
                        IMMA16832(c[mt][j], a[mt], b[j]);
            }
            if (l == 0) MBARRIER_ARRIVE(eb);          // warp done with stage s

            ps = s; pph = ph;
            if (++s == STAGES) { s = 0; ph ^= 1; }
        }

        // ---- Epilogue: sB[col] scale, segmented max, sA[row] scale ----
        float* epi = reinterpret_cast<float*>(smem + SMEM_EPI) + ebuf * 256;
        int col0 = warp_n * 64 + 2 * (l & 3);
#pragma unroll
        for (int mt = 0; mt < 4; mt++) {
            float mlo = -1e30f, mhi = -1e30f;
#pragma unroll
            for (int j = 0; j < 8; j++) {
                float s0 = __ldg(&sB[n0 + col0 + j * 8]);
                float s1 = __ldg(&sB[n0 + col0 + j * 8 + 1]);
                mlo = fmaxf(mlo, fmaxf((float)c[mt][j][0] * s0, (float)c[mt][j][1] * s1));
                mhi = fmaxf(mhi, fmaxf((float)c[mt][j][2] * s0, (float)c[mt][j][3] * s1));
            }
            mlo = fmaxf(mlo, __shfl_xor_sync(0xFFFFFFFFu, mlo, 1));
            mlo = fmaxf(mlo, __shfl_xor_sync(0xFFFFFFFFu, mlo, 2));
            mhi = fmaxf(mhi, __shfl_xor_sync(0xFFFFFFFFu, mhi, 1));
            mhi = fmaxf(mhi, __shfl_xor_sync(0xFFFFFFFFu, mhi, 2));
            if ((l & 3) == 0) {
                int rlo = mt * 16 + (l >> 2);
                epi[warp_n * 64 + rlo]     = mlo;
                epi[warp_n * 64 + rlo + 8] = mhi;
            }
        }
        __syncthreads();    // single barrier per tile (epi is double-buffered)

        if (tid < 64) {
            float v = fmaxf(fmaxf(epi[tid], epi[64 + tid]),
                            fmaxf(epi[128 + tid], epi[192 + tid]));
            float dot = v * __ldg(&sA[m0 + tid]);
            float sq = fmaxf(2.0f - 2.0f * dot, 1e-12f);
            out[(size_t)(m0 + tid) * num_tasks + (t / n_mtiles)] = -sqrtf(sq);
        }
        ebuf ^= 1;
    }
}

// ============================================================================
// Host side
// ============================================================================
typedef CUresult (*EncodeFn)(CUtensorMap*, CUtensorMapDataType, cuuint32_t, void*,
                             const cuuint64_t*, const cuuint64_t*, const cuuint32_t*,
                             const cuuint32_t*, CUtensorMapInterleave, CUtensorMapSwizzle,
                             CUtensorMapL2promotion, CUtensorMapFloatOOBfill);

static void encode_2d(EncodeFn enc, CUtensorMap* tm, void* ptr,
                      uint64_t rows, uint32_t box_rows) {
    cuuint64_t dims[2]    = {D_DIM, rows};
    cuuint64_t strides[1] = {D_DIM};              // int8: 1024 bytes per row
    cuuint32_t box[2]     = {K_TILE, box_rows};   // 64 int8 = 64B = SW64 span
    cuuint32_t es[2]      = {1, 1};
    enc(tm, CU_TENSOR_MAP_DATA_TYPE_UINT8, 2, ptr, dims, strides, box, es,
        CU_TENSOR_MAP_INTERLEAVE_NONE, CU_TENSOR_MAP_SWIZZLE_64B,
        CU_TENSOR_MAP_L2_PROMOTION_L2_128B, CU_TENSOR_MAP_FLOAT_OOB_FILL_NONE);
}

extern "C" void kernel_launch(void* const* d_in, const int* in_sizes, int n_in,
                              void* d_out, int out_size) {
    const float* x = (const float*)d_in[0];
    const float* w = (const float*)d_in[1];
    const int B  = in_sizes[0] / D_DIM;   // 8192
    const int TS = in_sizes[1] / D_DIM;   // 5120
    const int T  = TS / 256;              // 20
    float* out = (float*)d_out;

    int8_t *dXq = nullptr, *dWq = nullptr;
    float *dsX = nullptr, *dsW = nullptr;
    cudaGetSymbolAddress((void**)&dXq, g_Xq);
    cudaGetSymbolAddress((void**)&dWq, g_Wq);
    cudaGetSymbolAddress((void**)&dsX, g_sX);
    cudaGetSymbolAddress((void**)&dsW, g_sW);

    normquant_kernel<<<(B + TS) / 4, 256>>>(x, w, dXq, dWq, dsX, dsW, B);

    void* fn = nullptr;
    cudaDriverEntryPointQueryResult qr;
    cudaGetDriverEntryPoint("cuTensorMapEncodeTiled", &fn, cudaEnableDefault, &qr);
    EncodeFn enc = (EncodeFn)fn;

    CUtensorMap tma_a, tma_b;
    encode_2d(enc, &tma_a, dXq, (uint64_t)B,  M_TILE);
    encode_2d(enc, &tma_b, dWq, (uint64_t)TS, N_TILE);

    int nsm = 148;
    cudaDeviceGetAttribute(&nsm, cudaDevAttrMultiProcessorCount, 0);

    int n_mtiles = B / M_TILE;            // 128
    int total_tiles = n_mtiles * T;       // 2560

    cudaFuncSetAttribute(gemm_segmax_kernel,
                         cudaFuncAttributeMaxDynamicSharedMemorySize, SMEM_TOTAL);
    gemm_segmax_kernel<<<2 * nsm, THREADS, SMEM_TOTAL>>>(
        tma_a, tma_b, dsX, dsW, out, T, n_mtiles, total_tiles);
}

// round 14
// speedup vs baseline: 1.0776x; 1.0776x over previous
#include <cuda_runtime.h>
#include <cuda.h>
#include <cuda_bf16.h>
#include <cstdint>

// ============================================================================
// Problem constants (fixed by setup_inputs: B=8192, D=1024, T=20, S=256)
// ============================================================================
#define D_DIM   1024
#define MAX_B   8192
#define MAX_TS  5120

#define M_TILE  128
#define N_TILE  256               // == BUFFER_SIZE -> segmented min is CTA-local
#define K_TILE  128               // int8: 128 elems = 128B = one SW128 atom row
#define NK      (D_DIM / K_TILE)  // 8 K-stages per tile
#define STAGES  4
#define NWC     8                 // 8 warps: 2(M) x 4(N), warp tile 64x64
#define THREADS (NWC * 32)        // 256

#define A_STAGE_BYTES (M_TILE * 128)                    // 16384
#define B_STAGE_BYTES (N_TILE * 128)                    // 32768
#define STAGE_BYTES   (A_STAGE_BYTES + B_STAGE_BYTES)   // 49152

#define SMEM_FULL   0                      // 4 x 8B mbarriers
#define SMEM_EMPTY  32                     // 4 x 8B mbarriers
#define SMEM_EPI    64                     // 2 buffers x 512 floats = 4096
#define SMEM_A      8192                   // 1024-aligned
#define SMEM_B      (SMEM_A + STAGES * A_STAGE_BYTES)
#define SMEM_TOTAL  (SMEM_B + STAGES * B_STAGE_BYTES)

// ============================================================================
// Scratch (module-load allocation, legal under _HX_ENFORCE)
// ============================================================================
__device__ __align__(1024) int8_t g_Xq[MAX_B * D_DIM];
__device__ __align__(1024) int8_t g_Wq[MAX_TS * D_DIM];
__device__ float g_sX[MAX_B];
__device__ float g_sW[MAX_TS];

// ============================================================================
// PTX helpers (base sm_80/sm_90 ISA only — target is sm_100 base, no tcgen05)
// ============================================================================
__device__ __forceinline__ uint32_t smem_u32(const void* p) {
    uint32_t a;
    asm("{ .reg .u64 t; cvta.to.shared.u64 t, %1; cvt.u32.u64 %0, t; }"
        : "=r"(a) : "l"(p));
    return a;
}

#define MBARRIER_INIT(mbar, cnt) \
    asm volatile("mbarrier.init.shared.b64 [%0], %1;" \
                 :: "r"((uint32_t)(mbar)), "r"((uint32_t)(cnt)) : "memory")
#define MBARRIER_EXPECT_TX(mbar, bytes) \
    asm volatile("mbarrier.arrive.expect_tx.shared.b64 _, [%0], %1;" \
                 :: "r"((uint32_t)(mbar)), "r"((uint32_t)(bytes)) : "memory")
#define MBARRIER_ARRIVE(mbar) \
    asm volatile("mbarrier.arrive.shared.b64 _, [%0];" \
                 :: "r"((uint32_t)(mbar)) : "memory")

#define MBARRIER_WAIT_PARITY(mbar, parity) do {                                  \
    uint32_t _m = (uint32_t)(mbar);                                              \
    uint32_t _p = (uint32_t)(parity);                                            \
    uint32_t _done;                                                              \
    asm volatile("{\n\t.reg .pred p;\n\t"                                        \
        "mbarrier.try_wait.parity.acquire.cta.shared::cta.b64 p, [%1], %2;\n\t"  \
        "selp.b32 %0, 1, 0, p;\n\t}"                                             \
        : "=r"(_done) : "r"(_m), "r"(_p) : "memory");                            \
    if (!_done) {                                                                \
        asm volatile("{\n\t.reg .pred P1;\n\t"                                   \
            "WAIT_LOOP_%=:\n\t"                                                  \
            "mbarrier.try_wait.parity.acquire.cta.shared::cta.b64 P1, [%0], %1, 0x989680;\n\t" \
            "@P1 bra.uni WAIT_DONE_%=;\n\t"                                      \
            "bra.uni WAIT_LOOP_%=;\n\t"                                          \
            "WAIT_DONE_%=:\n\t}"                                                 \
            :: "r"(_m), "r"(_p) : "memory");                                     \
    }                                                                            \
} while (0)

#define TMA_LOAD_2D(smem_addr, tmap, cx, cy, mbar) \
    asm volatile("cp.async.bulk.tensor.2d.shared::cluster.global.tile.mbarrier::complete_tx::bytes " \
                 "[%0], [%1, {%2, %3}], [%4];" \
                 :: "r"((uint32_t)(smem_addr)), "l"(tmap), \
                    "r"((int)(cx)), "r"((int)(cy)), "r"((uint32_t)(mbar)) : "memory")

#define LDSM_X4(r0, r1, r2, r3, addr) \
    asm volatile("ldmatrix.sync.aligned.m8n8.x4.shared.b16 {%0,%1,%2,%3}, [%4];" \
                 : "=r"(r0), "=r"(r1), "=r"(r2), "=r"(r3) : "r"(addr))

// int8 IMMA: byte-identical fragment layout to HMMA m16n8k16 with f16 -> 2 x s8
#define IMMA16832(c, a, b) \
    asm volatile("mma.sync.aligned.m16n8k32.row.col.s32.s8.s8.s32 " \
                 "{%0,%1,%2,%3}, {%4,%5,%6,%7}, {%8,%9}, {%0,%1,%2,%3};" \
                 : "+r"((c)[0]), "+r"((c)[1]), "+r"((c)[2]), "+r"((c)[3]) \
                 : "r"((a)[0]), "r"((a)[1]), "r"((a)[2]), "r"((a)[3]), \
                   "r"((b)[0]), "r"((b)[1]))

#define SWZ128(x) ((x) ^ (((x) >> 3) & 0x70))

// ============================================================================
// Kernel 1: fused L2-normalize + per-row symmetric int8 quantize.
// 4 rows per 256-thread block; 64 threads/row; 4 float4 loads/thread (MLP=4).
// ============================================================================
__global__ void __launch_bounds__(256) normquant_kernel(
    const float* __restrict__ x, const float* __restrict__ w,
    int8_t* __restrict__ xq, int8_t* __restrict__ wq,
    float* __restrict__ sx, float* __restrict__ sw, int B) {
    int rid  = blockIdx.x * 4 + (threadIdx.x >> 6);   // global row id
    int lane = threadIdx.x & 63;                      // 0..63 within row group
    bool isX = rid < B;
    const float* in = isX ? x : w;
    int row = isX ? rid : rid - B;
    int8_t* outq = isX ? xq : wq;
    float* outs  = isX ? sx : sw;

    const float4* src = reinterpret_cast<const float4*>(in) + (size_t)row * 256;
    float4 v[4];
#pragma unroll
    for (int j = 0; j < 4; j++) v[j] = src[lane + j * 64];

    float ss = 0.0f, ma = 0.0f;
#pragma unroll
    for (int j = 0; j < 4; j++) {
        ss += v[j].x * v[j].x + v[j].y * v[j].y + v[j].z * v[j].z + v[j].w * v[j].w;
        ma = fmaxf(ma, fmaxf(fmaxf(fabsf(v[j].x), fabsf(v[j].y)),
                             fmaxf(fabsf(v[j].z), fabsf(v[j].w))));
    }
#pragma unroll
    for (int o = 16; o > 0; o >>= 1) {
        ss += __shfl_xor_sync(0xFFFFFFFFu, ss, o);
        ma = fmaxf(ma, __shfl_xor_sync(0xFFFFFFFFu, ma, o));
    }
    __shared__ float wss[4][2], wma[4][2];
    int rgrp = threadIdx.x >> 6;
    int wslot = (threadIdx.x >> 5) & 1;
    if ((threadIdx.x & 31) == 0) { wss[rgrp][wslot] = ss; wma[rgrp][wslot] = ma; }
    __syncthreads();
    float tot = wss[rgrp][0] + wss[rgrp][1];
    float mx  = fmaxf(wma[rgrp][0], wma[rgrp][1]);

    float rq = 127.0f / mx;
    uint32_t* dst = reinterpret_cast<uint32_t*>(outq) + (size_t)row * 256;
#pragma unroll
    for (int j = 0; j < 4; j++) {
        int q0 = __float2int_rn(v[j].x * rq), q1 = __float2int_rn(v[j].y * rq);
        int q2 = __float2int_rn(v[j].z * rq), q3 = __float2int_rn(v[j].w * rq);
        dst[lane + j * 64] = (uint32_t)(q0 & 0xFF) | ((uint32_t)(q1 & 0xFF) << 8) |
                             ((uint32_t)(q2 & 0xFF) << 16) | ((uint32_t)(q3 & 0xFF) << 24);
    }
    if (lane == 0) outs[row] = mx * rsqrtf(tot) / 127.0f;
}

// ============================================================================
// Kernel 2: PERSISTENT IMMA GEMM (round-12 winner) + peeled final K-stage:
// after the last stage's full-wait, scale loads (sB x16, sA x1) are issued
// BEFORE the stage's LDSM/IMMA body so their L2 latency hides under compute.
// Lagged refill: at iter g top, tid 0 waits on empty of stage g-1 and loads
// stage g-1+4 (global-stage based -> unaffected by the peel).
// ============================================================================
__global__ void __launch_bounds__(THREADS, 1) gemm_segmax_kernel(
    const __grid_constant__ CUtensorMap tma_a,
    const __grid_constant__ CUtensorMap tma_b,
    const float* __restrict__ sA, const float* __restrict__ sB,
    float* __restrict__ out, int num_tasks, int n_mtiles, int total_tiles) {
    extern __shared__ char smem[];
    uint32_t sb = smem_u32(smem);
    int tid = threadIdx.x;
    int wid = tid >> 5;
    int l   = tid & 31;
    int warp_m = wid >> 2;   // 0..1 -> rows warp_m*64
    int warp_n = wid & 3;    // 0..3 -> cols warp_n*64

    int ntile_cta = 0;
    for (int t = blockIdx.x; t < total_tiles; t += gridDim.x) ntile_cta++;
    if (ntile_cta == 0) return;
    int total_stg = ntile_cta * NK;

    if (tid == 0) {
#pragma unroll
        for (int s = 0; s < STAGES; s++) {
            MBARRIER_INIT(sb + SMEM_FULL  + s * 8, 1);
            MBARRIER_INIT(sb + SMEM_EMPTY + s * 8, NWC);
        }
    }
    __syncthreads();

    // ---- Prologue: fill all 4 stages ----
    if (tid == 0) {
        int m0p = (blockIdx.x % n_mtiles) * M_TILE;
        int n0p = (blockIdx.x / n_mtiles) * N_TILE;
#pragma unroll
        for (int gg = 0; gg < STAGES; gg++) {
            uint32_t fb = sb + SMEM_FULL + gg * 8;
            MBARRIER_EXPECT_TX(fb, STAGE_BYTES);
            TMA_LOAD_2D(sb + SMEM_A + gg * A_STAGE_BYTES, &tma_a, gg * K_TILE, m0p, fb);
            TMA_LOAD_2D(sb + SMEM_B + gg * B_STAGE_BYTES, &tma_b, gg * K_TILE, n0p, fb);
        }
    }

    // Lane-invariant byte offsets within a stage tile (row stride 128B)
    uint32_t aoff[4];
#pragma unroll
    for (int mt = 0; mt < 4; mt++)
        aoff[mt] = (uint32_t)(warp_m * 64 + mt * 16 + (l & 15)) * 128 + ((l >> 4) & 1) * 16;
    uint32_t boff[4];
#pragma unroll
    for (int jp = 0; jp < 4; jp++)
        boff[jp] = (uint32_t)(warp_n * 64 + jp * 16 + ((l & 16) >> 1) + (l & 7)) * 128
                 + ((l & 8) ? 16u : 0u);

    int g = 0;                               // global stage counter
    int ebuf = 0;                            // epilogue buffer selector
    for (int t = blockIdx.x; t < total_tiles; t += gridDim.x) {
        int m0 = (t % n_mtiles) * M_TILE;
        int n0 = (t / n_mtiles) * N_TILE;

        int c[4][8][4];
#pragma unroll
        for (int mt = 0; mt < 4; mt++)
#pragma unroll
            for (int j = 0; j < 8; j++)
#pragma unroll
                for (int i = 0; i < 4; i++) c[mt][j][i] = 0;

        // ---- Mainloop: stages 0 .. NK-2 ----
#pragma unroll 1
        for (int kt = 0; kt < NK - 1; kt++, g++) {
            int s = g & (STAGES - 1);
            int ph = (g >> 2) & 1;
            uint32_t fb = sb + SMEM_FULL  + s * 8;
            uint32_t eb = sb + SMEM_EMPTY + s * 8;

            // lagged refill: stage consumed LAST iteration (g-1)
            if (tid == 0 && g > 0) {
                int gp = g - 1;
                int gr = gp + STAGES;
                if (gr < total_stg) {
                    int sp  = gp & (STAGES - 1);
                    int php = (gp >> 2) & 1;
                    uint32_t ebp = sb + SMEM_EMPTY + sp * 8;
                    uint32_t fbp = sb + SMEM_FULL  + sp * 8;
                    MBARRIER_WAIT_PARITY(ebp, php);
                    int tt = gr / NK, ktt = gr % NK;
                    int tgl = blockIdx.x + tt * gridDim.x;
                    MBARRIER_EXPECT_TX(fbp, STAGE_BYTES);
                    TMA_LOAD_2D(sb + SMEM_A + sp * A_STAGE_BYTES, &tma_a,
                                ktt * K_TILE, (tgl % n_mtiles) * M_TILE, fbp);
                    TMA_LOAD_2D(sb + SMEM_B + sp * B_STAGE_BYTES, &tma_b,
                                ktt * K_TILE, (tgl / n_mtiles) * N_TILE, fbp);
                }
            }

            MBARRIER_WAIT_PARITY(fb, ph);

            uint32_t a_sb = sb + SMEM_A + s * A_STAGE_BYTES;
            uint32_t b_sb = sb + SMEM_B + s * B_STAGE_BYTES;

#pragma unroll
            for (int ks = 0; ks < 4; ks++) {          // 4 x k32 per 128B stage
                uint32_t a[4][4];
#pragma unroll
                for (int mt = 0; mt < 4; mt++) {
                    uint32_t off = aoff[mt] + ks * 32;
                    LDSM_X4(a[mt][0], a[mt][1], a[mt][2], a[mt][3], a_sb + SWZ128(off));
                }
                uint32_t b[8][2];
#pragma unroll
                for (int jp = 0; jp < 4; jp++) {
                    uint32_t off = boff[jp] + ks * 32;
                    LDSM_X4(b[2 * jp][0], b[2 * jp][1], b[2 * jp + 1][0], b[2 * jp + 1][1],
                            b_sb + SWZ128(off));
                }
#pragma unroll
                for (int mt = 0; mt < 4; mt++)
#pragma unroll
                    for (int j = 0; j < 8; j++)
                        IMMA16832(c[mt][j], a[mt], b[j]);
            }
            if (l == 0) MBARRIER_ARRIVE(eb);          // warp done with stage s
        }

        // ---- Peeled final stage: scale prefetch hides under compute ----
        int col0 = warp_n * 64 + 2 * (l & 3);
        float sv0[8], sv1[8], sav;
        {
            int s = g & (STAGES - 1);
            int ph = (g >> 2) & 1;
            uint32_t fb = sb + SMEM_FULL  + s * 8;
            uint32_t eb = sb + SMEM_EMPTY + s * 8;

            if (tid == 0) {   // lagged refill for stage g-1 (g >= 7 here)
                int gp = g - 1;
                int gr = gp + STAGES;
                if (gr < total_stg) {
                    int sp  = gp & (STAGES - 1);
                    int php = (gp >> 2) & 1;
                    uint32_t ebp = sb + SMEM_EMPTY + sp * 8;
                    uint32_t fbp = sb + SMEM_FULL  + sp * 8;
                    MBARRIER_WAIT_PARITY(ebp, php);
                    int tt = gr / NK, ktt = gr % NK;
                    int tgl = blockIdx.x + tt * gridDim.x;
                    MBARRIER_EXPECT_TX(fbp, STAGE_BYTES);
                    TMA_LOAD_2D(sb + SMEM_A + sp * A_STAGE_BYTES, &tma_a,
                                ktt * K_TILE, (tgl % n_mtiles) * M_TILE, fbp);
                    TMA_LOAD_2D(sb + SMEM_B + sp * B_STAGE_BYTES, &tma_b,
                                ktt * K_TILE, (tgl / n_mtiles) * N_TILE, fbp);
                }
            }

            MBARRIER_WAIT_PARITY(fb, ph);

            // EARLY scale loads — latency overlaps the stage body below
#pragma unroll
            for (int j = 0; j < 8; j++) {
                sv0[j] = __ldg(&sB[n0 + col0 + j * 8]);
                sv1[j] = __ldg(&sB[n0 + col0 + j * 8 + 1]);
            }
            sav = __ldg(&sA[m0 + (tid & 127)]);

            uint32_t a_sb = sb + SMEM_A + s * A_STAGE_BYTES;
            uint32_t b_sb = sb + SMEM_B + s * B_STAGE_BYTES;

#pragma unroll
            for (int ks = 0; ks < 4; ks++) {
                uint32_t a[4][4];
#pragma unroll
                for (int mt = 0; mt < 4; mt++) {
                    uint32_t off = aoff[mt] + ks * 32;
                    LDSM_X4(a[mt][0], a[mt][1], a[mt][2], a[mt][3], a_sb + SWZ128(off));
                }
                uint32_t b[8][2];
#pragma unroll
                for (int jp = 0; jp < 4; jp++) {
                    uint32_t off = boff[jp] + ks * 32;
                    LDSM_X4(b[2 * jp][0], b[2 * jp][1], b[2 * jp + 1][0], b[2 * jp + 1][1],
                            b_sb + SWZ128(off));
                }
#pragma unroll
                for (int mt = 0; mt < 4; mt++)
#pragma unroll
                    for (int j = 0; j < 8; j++)
                        IMMA16832(c[mt][j], a[mt], b[j]);
            }
            if (l == 0) MBARRIER_ARRIVE(eb);
            g++;
        }

        // ---- Epilogue: sB[col] scale, segmented max, sA[row] scale ----
        float* epi = reinterpret_cast<float*>(smem + SMEM_EPI) + ebuf * 512;
#pragma unroll
        for (int mt = 0; mt < 4; mt++) {
            float mlo = -1e30f, mhi = -1e30f;
#pragma unroll
            for (int j = 0; j < 8; j++) {
                mlo = fmaxf(mlo, fmaxf((float)c[mt][j][0] * sv0[j],
                                       (float)c[mt][j][1] * sv1[j]));
                mhi = fmaxf(mhi, fmaxf((float)c[mt][j][2] * sv0[j],
                                       (float)c[mt][j][3] * sv1[j]));
            }
            mlo = fmaxf(mlo, __shfl_xor_sync(0xFFFFFFFFu, mlo, 1));
            mlo = fmaxf(mlo, __shfl_xor_sync(0xFFFFFFFFu, mlo, 2));
            mhi = fmaxf(mhi, __shfl_xor_sync(0xFFFFFFFFu, mhi, 1));
            mhi = fmaxf(mhi, __shfl_xor_sync(0xFFFFFFFFu, mhi, 2));
            if ((l & 3) == 0) {
                int rlo = warp_m * 64 + mt * 16 + (l >> 2);
                epi[warp_n * 128 + rlo]     = mlo;
                epi[warp_n * 128 + rlo + 8] = mhi;
            }
        }
        __syncthreads();    // single barrier per tile (epi is double-buffered)

        if (tid < 128) {
            float v = fmaxf(fmaxf(epi[tid], epi[128 + tid]),
                            fmaxf(epi[256 + tid], epi[384 + tid]));
            float dot = v * sav;
            float sq = fmaxf(2.0f - 2.0f * dot, 1e-12f);
            out[(size_t)(m0 + tid) * num_tasks + (t / n_mtiles)] = -sqrtf(sq);
        }
        ebuf ^= 1;
    }
}

// ============================================================================
// Host side
// ============================================================================
typedef CUresult (*EncodeFn)(CUtensorMap*, CUtensorMapDataType, cuuint32_t, void*,
                             const cuuint64_t*, const cuuint64_t*, const cuuint32_t*,
                             const cuuint32_t*, CUtensorMapInterleave, CUtensorMapSwizzle,
                             CUtensorMapL2promotion, CUtensorMapFloatOOBfill);

static void encode_2d(EncodeFn enc, CUtensorMap* tm, void* ptr,
                      uint64_t rows, uint32_t box_rows) {
    cuuint64_t dims[2]    = {D_DIM, rows};
    cuuint64_t strides[1] = {D_DIM};              // int8: 1024 bytes per row
    cuuint32_t box[2]     = {K_TILE, box_rows};   // 128 int8 = 128B = SW128 span
    cuuint32_t es[2]      = {1, 1};
    enc(tm, CU_TENSOR_MAP_DATA_TYPE_UINT8, 2, ptr, dims, strides, box, es,
        CU_TENSOR_MAP_INTERLEAVE_NONE, CU_TENSOR_MAP_SWIZZLE_128B,
        CU_TENSOR_MAP_L2_PROMOTION_L2_128B, CU_TENSOR_MAP_FLOAT_OOB_FILL_NONE);
}

extern "C" void kernel_launch(void* const* d_in, const int* in_sizes, int n_in,
                              void* d_out, int out_size) {
    const float* x = (const float*)d_in[0];
    const float* w = (const float*)d_in[1];
    const int B  = in_sizes[0] / D_DIM;   // 8192
    const int TS = in_sizes[1] / D_DIM;   // 5120
    const int T  = TS / 256;              // 20
    float* out = (float*)d_out;

    int8_t *dXq = nullptr, *dWq = nullptr;
    float *dsX = nullptr, *dsW = nullptr;
    cudaGetSymbolAddress((void**)&dXq, g_Xq);
    cudaGetSymbolAddress((void**)&dWq, g_Wq);
    cudaGetSymbolAddress((void**)&dsX, g_sX);
    cudaGetSymbolAddress((void**)&dsW, g_sW);

    normquant_kernel<<<(B + TS) / 4, 256>>>(x, w, dXq, dWq, dsX, dsW, B);

    void* fn = nullptr;
    cudaDriverEntryPointQueryResult qr;
    cudaGetDriverEntryPoint("cuTensorMapEncodeTiled", &fn, cudaEnableDefault, &qr);
    EncodeFn enc = (EncodeFn)fn;

    CUtensorMap tma_a, tma_b;
    encode_2d(enc, &tma_a, dXq, (uint64_t)B,  M_TILE);
    encode_2d(enc, &tma_b, dWq, (uint64_t)TS, N_TILE);

    int nsm = 148;
    cudaDeviceGetAttribute(&nsm, cudaDevAttrMultiProcessorCount, 0);

    int n_mtiles = B / M_TILE;            // 64
    int total_tiles = n_mtiles * T;       // 1280

    cudaFuncSetAttribute(gemm_segmax_kernel,
                         cudaFuncAttributeMaxDynamicSharedMemorySize, SMEM_TOTAL);
    gemm_segmax_kernel<<<nsm, THREADS, SMEM_TOTAL>>>(
        tma_a, tma_b, dsX, dsW, out, T, n_mtiles, total_tiles);
}

// round 15
// speedup vs baseline: 1.0786x; 1.0009x over previous
#include <cuda_runtime.h>
#include <cuda.h>
#include <cuda_bf16.h>
#include <cstdint>

// ============================================================================
// Problem constants (fixed by setup_inputs: B=8192, D=1024, T=20, S=256)
// ============================================================================
#define D_DIM   1024
#define MAX_B   8192
#define MAX_TS  5120

#define M_TILE  128
#define N_TILE  256               // == BUFFER_SIZE -> segmented min is CTA-local
#define K_TILE  128               // int8: 128 elems = 128B = one SW128 atom row
#define NK      (D_DIM / K_TILE)  // 8 K-stages per tile
#define STAGES  4
#define NWC     8                 // 8 warps: 2(M) x 4(N), warp tile 64x64
#define THREADS (NWC * 32)        // 256

#define A_STAGE_BYTES (M_TILE * 128)                    // 16384
#define B_STAGE_BYTES (N_TILE * 128)                    // 32768
#define STAGE_BYTES   (A_STAGE_BYTES + B_STAGE_BYTES)   // 49152

#define SMEM_FULL   0                      // 4 x 8B mbarriers
#define SMEM_EMPTY  32                     // 4 x 8B mbarriers
#define SMEM_EPI    64                     // 2 buffers x 512 floats = 4096
#define SMEM_A      8192                   // 1024-aligned
#define SMEM_B      (SMEM_A + STAGES * A_STAGE_BYTES)
#define SMEM_TOTAL  (SMEM_B + STAGES * B_STAGE_BYTES)

// ============================================================================
// Scratch (module-load allocation, legal under _HX_ENFORCE)
// ============================================================================
__device__ __align__(1024) int8_t g_Xq[MAX_B * D_DIM];
__device__ __align__(1024) int8_t g_Wq[MAX_TS * D_DIM];
__device__ float g_sX[MAX_B];
__device__ float g_sW[MAX_TS];

// ============================================================================
// PTX helpers (base sm_80/sm_90 ISA only — target is sm_100 base, no tcgen05)
// ============================================================================
__device__ __forceinline__ uint32_t smem_u32(const void* p) {
    uint32_t a;
    asm("{ .reg .u64 t; cvta.to.shared.u64 t, %1; cvt.u32.u64 %0, t; }"
        : "=r"(a) : "l"(p));
    return a;
}

#define MBARRIER_INIT(mbar, cnt) \
    asm volatile("mbarrier.init.shared.b64 [%0], %1;" \
                 :: "r"((uint32_t)(mbar)), "r"((uint32_t)(cnt)) : "memory")
#define MBARRIER_EXPECT_TX(mbar, bytes) \
    asm volatile("mbarrier.arrive.expect_tx.shared.b64 _, [%0], %1;" \
                 :: "r"((uint32_t)(mbar)), "r"((uint32_t)(bytes)) : "memory")
#define MBARRIER_ARRIVE(mbar) \
    asm volatile("mbarrier.arrive.shared.b64 _, [%0];" \
                 :: "r"((uint32_t)(mbar)) : "memory")

#define MBARRIER_WAIT_PARITY(mbar, parity) do {                                  \
    uint32_t _m = (uint32_t)(mbar);                                              \
    uint32_t _p = (uint32_t)(parity);                                            \
    uint32_t _done;                                                              \
    asm volatile("{\n\t.reg .pred p;\n\t"                                        \
        "mbarrier.try_wait.parity.acquire.cta.shared::cta.b64 p, [%1], %2;\n\t"  \
        "selp.b32 %0, 1, 0, p;\n\t}"                                             \
        : "=r"(_done) : "r"(_m), "r"(_p) : "memory");                            \
    if (!_done) {                                                                \
        asm volatile("{\n\t.reg .pred P1;\n\t"                                   \
            "WAIT_LOOP_%=:\n\t"                                                  \
            "mbarrier.try_wait.parity.acquire.cta.shared::cta.b64 P1, [%0], %1, 0x989680;\n\t" \
            "@P1 bra.uni WAIT_DONE_%=;\n\t"                                      \
            "bra.uni WAIT_LOOP_%=;\n\t"                                          \
            "WAIT_DONE_%=:\n\t}"                                                 \
            :: "r"(_m), "r"(_p) : "memory");                                     \
    }                                                                            \
} while (0)

#define TMA_LOAD_2D(smem_addr, tmap, cx, cy, mbar) \
    asm volatile("cp.async.bulk.tensor.2d.shared::cluster.global.tile.mbarrier::complete_tx::bytes " \
                 "[%0], [%1, {%2, %3}], [%4];" \
                 :: "r"((uint32_t)(smem_addr)), "l"(tmap), \
                    "r"((int)(cx)), "r"((int)(cy)), "r"((uint32_t)(mbar)) : "memory")

#define LDSM_X4(r0, r1, r2, r3, addr) \
    asm volatile("ldmatrix.sync.aligned.m8n8.x4.shared.b16 {%0,%1,%2,%3}, [%4];" \
                 : "=r"(r0), "=r"(r1), "=r"(r2), "=r"(r3) : "r"(addr))

// int8 IMMA: byte-identical fragment layout to HMMA m16n8k16 with f16 -> 2 x s8
#define IMMA16832(c, a, b) \
    asm volatile("mma.sync.aligned.m16n8k32.row.col.s32.s8.s8.s32 " \
                 "{%0,%1,%2,%3}, {%4,%5,%6,%7}, {%8,%9}, {%0,%1,%2,%3};" \
                 : "+r"((c)[0]), "+r"((c)[1]), "+r"((c)[2]), "+r"((c)[3]) \
                 : "r"((a)[0]), "r"((a)[1]), "r"((a)[2]), "r"((a)[3]), \
                   "r"((b)[0]), "r"((b)[1]))

#define SWZ128(x) ((x) ^ (((x) >> 3) & 0x70))

// ============================================================================
// Kernel 1: fused L2-normalize + per-row symmetric int8 quantize.
// 4 rows per 256-thread block; 64 threads/row; 4 float4 loads/thread (MLP=4).
// ============================================================================
__global__ void __launch_bounds__(256) normquant_kernel(
    const float* __restrict__ x, const float* __restrict__ w,
    int8_t* __restrict__ xq, int8_t* __restrict__ wq,
    float* __restrict__ sx, float* __restrict__ sw, int B) {
    int rid  = blockIdx.x * 4 + (threadIdx.x >> 6);   // global row id
    int lane = threadIdx.x & 63;                      // 0..63 within row group
    bool isX = rid < B;
    const float* in = isX ? x : w;
    int row = isX ? rid : rid - B;
    int8_t* outq = isX ? xq : wq;
    float* outs  = isX ? sx : sw;

    const float4* src = reinterpret_cast<const float4*>(in) + (size_t)row * 256;
    float4 v[4];
#pragma unroll
    for (int j = 0; j < 4; j++) v[j] = src[lane + j * 64];

    float ss = 0.0f, ma = 0.0f;
#pragma unroll
    for (int j = 0; j < 4; j++) {
        ss += v[j].x * v[j].x + v[j].y * v[j].y + v[j].z * v[j].z + v[j].w * v[j].w;
        ma = fmaxf(ma, fmaxf(fmaxf(fabsf(v[j].x), fabsf(v[j].y)),
                             fmaxf(fabsf(v[j].z), fabsf(v[j].w))));
    }
#pragma unroll
    for (int o = 16; o > 0; o >>= 1) {
        ss += __shfl_xor_sync(0xFFFFFFFFu, ss, o);
        ma = fmaxf(ma, __shfl_xor_sync(0xFFFFFFFFu, ma, o));
    }
    __shared__ float wss[4][2], wma[4][2];
    int rgrp = threadIdx.x >> 6;
    int wslot = (threadIdx.x >> 5) & 1;
    if ((threadIdx.x & 31) == 0) { wss[rgrp][wslot] = ss; wma[rgrp][wslot] = ma; }
    __syncthreads();
    float tot = wss[rgrp][0] + wss[rgrp][1];
    float mx  = fmaxf(wma[rgrp][0], wma[rgrp][1]);

    float rq = 127.0f / mx;
    uint32_t* dst = reinterpret_cast<uint32_t*>(outq) + (size_t)row * 256;
#pragma unroll
    for (int j = 0; j < 4; j++) {
        int q0 = __float2int_rn(v[j].x * rq), q1 = __float2int_rn(v[j].y * rq);
        int q2 = __float2int_rn(v[j].z * rq), q3 = __float2int_rn(v[j].w * rq);
        dst[lane + j * 64] = (uint32_t)(q0 & 0xFF) | ((uint32_t)(q1 & 0xFF) << 8) |
                             ((uint32_t)(q2 & 0xFF) << 16) | ((uint32_t)(q3 & 0xFF) << 24);
    }
    if (lane == 0) outs[row] = mx * rsqrtf(tot) / 127.0f;
}

// ============================================================================
// Kernel 2: PERSISTENT IMMA GEMM (round-14 winner) + warp-staggered ks order:
// warp w consumes k32-steps in order (ks2 + wid) & 3, spreading the stage-
// start LDSM crossbar burst across 4 different k-slices (results identical:
// integer accumulation commutes). Peeled final K-stage prefetches scales
// before its compute body; lagged refill reloads stage g-1 at iter-g top.
// ============================================================================
__global__ void __launch_bounds__(THREADS, 1) gemm_segmax_kernel(
    const __grid_constant__ CUtensorMap tma_a,
    const __grid_constant__ CUtensorMap tma_b,
    const float* __restrict__ sA, const float* __restrict__ sB,
    float* __restrict__ out, int num_tasks, int n_mtiles, int total_tiles) {
    extern __shared__ char smem[];
    uint32_t sb = smem_u32(smem);
    int tid = threadIdx.x;
    int wid = tid >> 5;
    int l   = tid & 31;
    int warp_m = wid >> 2;   // 0..1 -> rows warp_m*64
    int warp_n = wid & 3;    // 0..3 -> cols warp_n*64

    int ntile_cta = 0;
    for (int t = blockIdx.x; t < total_tiles; t += gridDim.x) ntile_cta++;
    if (ntile_cta == 0) return;
    int total_stg = ntile_cta * NK;

    if (tid == 0) {
#pragma unroll
        for (int s = 0; s < STAGES; s++) {
            MBARRIER_INIT(sb + SMEM_FULL  + s * 8, 1);
            MBARRIER_INIT(sb + SMEM_EMPTY + s * 8, NWC);
        }
    }
    __syncthreads();

    // ---- Prologue: fill all 4 stages ----
    if (tid == 0) {
        int m0p = (blockIdx.x % n_mtiles) * M_TILE;
        int n0p = (blockIdx.x / n_mtiles) * N_TILE;
#pragma unroll
        for (int gg = 0; gg < STAGES; gg++) {
            uint32_t fb = sb + SMEM_FULL + gg * 8;
            MBARRIER_EXPECT_TX(fb, STAGE_BYTES);
            TMA_LOAD_2D(sb + SMEM_A + gg * A_STAGE_BYTES, &tma_a, gg * K_TILE, m0p, fb);
            TMA_LOAD_2D(sb + SMEM_B + gg * B_STAGE_BYTES, &tma_b, gg * K_TILE, n0p, fb);
        }
    }

    // Lane-invariant byte offsets within a stage tile (row stride 128B)
    uint32_t aoff[4];
#pragma unroll
    for (int mt = 0; mt < 4; mt++)
        aoff[mt] = (uint32_t)(warp_m * 64 + mt * 16 + (l & 15)) * 128 + ((l >> 4) & 1) * 16;
    uint32_t boff[4];
#pragma unroll
    for (int jp = 0; jp < 4; jp++)
        boff[jp] = (uint32_t)(warp_n * 64 + jp * 16 + ((l & 16) >> 1) + (l & 7)) * 128
                 + ((l & 8) ? 16u : 0u);

    int g = 0;                               // global stage counter
    int ebuf = 0;                            // epilogue buffer selector
    for (int t = blockIdx.x; t < total_tiles; t += gridDim.x) {
        int m0 = (t % n_mtiles) * M_TILE;
        int n0 = (t / n_mtiles) * N_TILE;

        int c[4][8][4];
#pragma unroll
        for (int mt = 0; mt < 4; mt++)
#pragma unroll
            for (int j = 0; j < 8; j++)
#pragma unroll
                for (int i = 0; i < 4; i++) c[mt][j][i] = 0;

        // ---- Mainloop: stages 0 .. NK-2 ----
#pragma unroll 1
        for (int kt = 0; kt < NK - 1; kt++, g++) {
            int s = g & (STAGES - 1);
            int ph = (g >> 2) & 1;
            uint32_t fb = sb + SMEM_FULL  + s * 8;
            uint32_t eb = sb + SMEM_EMPTY + s * 8;

            // lagged refill: stage consumed LAST iteration (g-1)
            if (tid == 0 && g > 0) {
                int gp = g - 1;
                int gr = gp + STAGES;
                if (gr < total_stg) {
                    int sp  = gp & (STAGES - 1);
                    int php = (gp >> 2) & 1;
                    uint32_t ebp = sb + SMEM_EMPTY + sp * 8;
                    uint32_t fbp = sb + SMEM_FULL  + sp * 8;
                    MBARRIER_WAIT_PARITY(ebp, php);
                    int tt = gr / NK, ktt = gr % NK;
                    int tgl = blockIdx.x + tt * gridDim.x;
                    MBARRIER_EXPECT_TX(fbp, STAGE_BYTES);
                    TMA_LOAD_2D(sb + SMEM_A + sp * A_STAGE_BYTES, &tma_a,
                                ktt * K_TILE, (tgl % n_mtiles) * M_TILE, fbp);
                    TMA_LOAD_2D(sb + SMEM_B + sp * B_STAGE_BYTES, &tma_b,
                                ktt * K_TILE, (tgl / n_mtiles) * N_TILE, fbp);
                }
            }

            MBARRIER_WAIT_PARITY(fb, ph);

            uint32_t a_sb = sb + SMEM_A + s * A_STAGE_BYTES;
            uint32_t b_sb = sb + SMEM_B + s * B_STAGE_BYTES;

#pragma unroll
            for (int ks2 = 0; ks2 < 4; ks2++) {       // warp-staggered k32 order
                int ks = (ks2 + wid) & 3;
                uint32_t a[4][4];
#pragma unroll
                for (int mt = 0; mt < 4; mt++) {
                    uint32_t off = aoff[mt] + ks * 32;
                    LDSM_X4(a[mt][0], a[mt][1], a[mt][2], a[mt][3], a_sb + SWZ128(off));
                }
                uint32_t b[8][2];
#pragma unroll
                for (int jp = 0; jp < 4; jp++) {
                    uint32_t off = boff[jp] + ks * 32;
                    LDSM_X4(b[2 * jp][0], b[2 * jp][1], b[2 * jp + 1][0], b[2 * jp + 1][1],
                            b_sb + SWZ128(off));
                }
#pragma unroll
                for (int mt = 0; mt < 4; mt++)
#pragma unroll
                    for (int j = 0; j < 8; j++)
                        IMMA16832(c[mt][j], a[mt], b[j]);
            }
            if (l == 0) MBARRIER_ARRIVE(eb);          // warp done with stage s
        }

        // ---- Peeled final stage: scale prefetch hides under compute ----
        int col0 = warp_n * 64 + 2 * (l & 3);
        float sv0[8], sv1[8], sav;
        {
            int s = g & (STAGES - 1);
            int ph = (g >> 2) & 1;
            uint32_t fb = sb + SMEM_FULL  + s * 8;
            uint32_t eb = sb + SMEM_EMPTY + s * 8;

            if (tid == 0) {   // lagged refill for stage g-1
                int gp = g - 1;
                int gr = gp + STAGES;
                if (gr < total_stg) {
                    int sp  = gp & (STAGES - 1);
                    int php = (gp >> 2) & 1;
                    uint32_t ebp = sb + SMEM_EMPTY + sp * 8;
                    uint32_t fbp = sb + SMEM_FULL  + sp * 8;
                    MBARRIER_WAIT_PARITY(ebp, php);
                    int tt = gr / NK, ktt = gr % NK;
                    int tgl = blockIdx.x + tt * gridDim.x;
                    MBARRIER_EXPECT_TX(fbp, STAGE_BYTES);
                    TMA_LOAD_2D(sb + SMEM_A + sp * A_STAGE_BYTES, &tma_a,
                                ktt * K_TILE, (tgl % n_mtiles) * M_TILE, fbp);
                    TMA_LOAD_2D(sb + SMEM_B + sp * B_STAGE_BYTES, &tma_b,
                                ktt * K_TILE, (tgl / n_mtiles) * N_TILE, fbp);
                }
            }

            MBARRIER_WAIT_PARITY(fb, ph);

            // EARLY scale loads — latency overlaps the stage body below
#pragma unroll
            for (int j = 0; j < 8; j++) {
                sv0[j] = __ldg(&sB[n0 + col0 + j * 8]);
                sv1[j] = __ldg(&sB[n0 + col0 + j * 8 + 1]);
            }
            sav = __ldg(&sA[m0 + (tid & 127)]);

            uint32_t a_sb = sb + SMEM_A + s * A_STAGE_BYTES;
            uint32_t b_sb = sb + SMEM_B + s * B_STAGE_BYTES;

#pragma unroll
            for (int ks2 = 0; ks2 < 4; ks2++) {       // warp-staggered k32 order
                int ks = (ks2 + wid) & 3;
                uint32_t a[4][4];
#pragma unroll
                for (int mt = 0; mt < 4; mt++) {
                    uint32_t off = aoff[mt] + ks * 32;
                    LDSM_X4(a[mt][0], a[mt][1], a[mt][2], a[mt][3], a_sb + SWZ128(off));
                }
                uint32_t b[8][2];
#pragma unroll
                for (int jp = 0; jp < 4; jp++) {
                    uint32_t off = boff[jp] + ks * 32;
                    LDSM_X4(b[2 * jp][0], b[2 * jp][1], b[2 * jp + 1][0], b[2 * jp + 1][1],
                            b_sb + SWZ128(off));
                }
#pragma unroll
                for (int mt = 0; mt < 4; mt++)
#pragma unroll
                    for (int j = 0; j < 8; j++)
                        IMMA16832(c[mt][j], a[mt], b[j]);
            }
            if (l == 0) MBARRIER_ARRIVE(eb);
            g++;
        }

        // ---- Epilogue: sB[col] scale, segmented max, sA[row] scale ----
        float* epi = reinterpret_cast<float*>(smem + SMEM_EPI) + ebuf * 512;
#pragma unroll
        for (int mt = 0; mt < 4; mt++) {
            float mlo = -1e30f, mhi = -1e30f;
#pragma unroll
            for (int j = 0; j < 8; j++) {
                mlo = fmaxf(mlo, fmaxf((float)c[mt][j][0] * sv0[j],
                                       (float)c[mt][j][1] * sv1[j]));
                mhi = fmaxf(mhi, fmaxf((float)c[mt][j][2] * sv0[j],
                                       (float)c[mt][j][3] * sv1[j]));
            }
            mlo = fmaxf(mlo, __shfl_xor_sync(0xFFFFFFFFu, mlo, 1));
            mlo = fmaxf(mlo, __shfl_xor_sync(0xFFFFFFFFu, mlo, 2));
            mhi = fmaxf(mhi, __shfl_xor_sync(0xFFFFFFFFu, mhi, 1));
            mhi = fmaxf(mhi, __shfl_xor_sync(0xFFFFFFFFu, mhi, 2));
            if ((l & 3) == 0) {
                int rlo = warp_m * 64 + mt * 16 + (l >> 2);
                epi[warp_n * 128 + rlo]     = mlo;
                epi[warp_n * 128 + rlo + 8] = mhi;
            }
        }
        __syncthreads();    // single barrier per tile (epi is double-buffered)

        if (tid < 128) {
            float v = fmaxf(fmaxf(epi[tid], epi[128 + tid]),
                            fmaxf(epi[256 + tid], epi[384 + tid]));
            float dot = v * sav;
            float sq = fmaxf(2.0f - 2.0f * dot, 1e-12f);
            out[(size_t)(m0 + tid) * num_tasks + (t / n_mtiles)] = -sqrtf(sq);
        }
        ebuf ^= 1;
    }
}

// ============================================================================
// Host side
// ============================================================================
typedef CUresult (*EncodeFn)(CUtensorMap*, CUtensorMapDataType, cuuint32_t, void*,
                             const cuuint64_t*, const cuuint64_t*, const cuuint32_t*,
                             const cuuint32_t*, CUtensorMapInterleave, CUtensorMapSwizzle,
                             CUtensorMapL2promotion, CUtensorMapFloatOOBfill);

static void encode_2d(EncodeFn enc, CUtensorMap* tm, void* ptr,
                      uint64_t rows, uint32_t box_rows) {
    cuuint64_t dims[2]    = {D_DIM, rows};
    cuuint64_t strides[1] = {D_DIM};              // int8: 1024 bytes per row
    cuuint32_t box[2]     = {K_TILE, box_rows};   // 128 int8 = 128B = SW128 span
    cuuint32_t es[2]      = {1, 1};
    enc(tm, CU_TENSOR_MAP_DATA_TYPE_UINT8, 2, ptr, dims, strides, box, es,
        CU_TENSOR_MAP_INTERLEAVE_NONE, CU_TENSOR_MAP_SWIZZLE_128B,
        CU_TENSOR_MAP_L2_PROMOTION_L2_128B, CU_TENSOR_MAP_FLOAT_OOB_FILL_NONE);
}

extern "C" void kernel_launch(void* const* d_in, const int* in_sizes, int n_in,
                              void* d_out, int out_size) {
    const float* x = (const float*)d_in[0];
    const float* w = (const float*)d_in[1];
    const int B  = in_sizes[0] / D_DIM;   // 8192
    const int TS = in_sizes[1] / D_DIM;   // 5120
    const int T  = TS / 256;              // 20
    float* out = (float*)d_out;

    int8_t *dXq = nullptr, *dWq = nullptr;
    float *dsX = nullptr, *dsW = nullptr;
    cudaGetSymbolAddress((void**)&dXq, g_Xq);
    cudaGetSymbolAddress((void**)&dWq, g_Wq);
    cudaGetSymbolAddress((void**)&dsX, g_sX);
    cudaGetSymbolAddress((void**)&dsW, g_sW);

    normquant_kernel<<<(B + TS) / 4, 256>>>(x, w, dXq, dWq, dsX, dsW, B);

    void* fn = nullptr;
    cudaDriverEntryPointQueryResult qr;
    cudaGetDriverEntryPoint("cuTensorMapEncodeTiled", &fn, cudaEnableDefault, &qr);
    EncodeFn enc = (EncodeFn)fn;

    CUtensorMap tma_a, tma_b;
    encode_2d(enc, &tma_a, dXq, (uint64_t)B,  M_TILE);
    encode_2d(enc, &tma_b, dWq, (uint64_t)TS, N_TILE);

    int nsm = 148;
    cudaDeviceGetAttribute(&nsm, cudaDevAttrMultiProcessorCount, 0);

    int n_mtiles = B / M_TILE;            // 64
    int total_tiles = n_mtiles * T;       // 1280

    cudaFuncSetAttribute(gemm_segmax_kernel,
                         cudaFuncAttributeMaxDynamicSharedMemorySize, SMEM_TOTAL);
    gemm_segmax_kernel<<<nsm, THREADS, SMEM_TOTAL>>>(
        tma_a, tma_b, dsX, dsW, out, T, n_mtiles, total_tiles);
}